// round 14
// baseline (speedup 1.0000x reference)
#include <cuda_runtime.h>
#include <cstdint>

#define E_DIM 512
#define W_DIM 16
#define FRAMES 16000
#define NBC 16
#define OUT_PER_BC 128008
#define GROUPS_PER_BC 1000
#define CTAS_PER_BC 27
#define NCTA (NBC * CTAS_PER_BC)                  // 432 <= 444 -> single wave
#define TPB 128
#define RS 4                                      // ring slots per warp (4 KB each)

// dynamic smem layout
#define SM_RAW   0                                // 4 warps * RS * 4096 = 65536
#define SM_PART  65536                            // [2][4][16][16] f32 = 8192
#define SM_EST   73728                            // [2][16][16] f32 = 2048
#define SM_CARRY 75776                            // 8 f32
#define SM_TOTAL 75808                            // 3 CTAs/SM

// per-CTA bl scratch: [cta][ks*4+ws][lane] uint4 (16 KB per CTA).
// Written by each thread in its prologue, read back (plain LDG, L1-hot)
// in the mainloop. No cross-CTA sharing -> no races, replay-deterministic.
__device__ __align__(16) uint4 gBloS[NCTA * 1024];

__device__ __forceinline__ uint32_t bf16hi2(float x0, float x1) {
    uint32_t h;
    asm("cvt.rn.bf16x2.f32 %0, %1, %2;" : "=r"(h) : "f"(x1), "f"(x0));
    return h;
}
__device__ __forceinline__ uint32_t bf16lo2(float x0, float x1, uint32_t h) {
    float h0 = __uint_as_float(h << 16);
    float h1 = __uint_as_float(h & 0xFFFF0000u);
    uint32_t l;
    asm("cvt.rn.bf16x2.f32 %0, %1, %2;" : "=r"(l) : "f"(x1 - h1), "f"(x0 - h0));
    return l;
}
__device__ __forceinline__ void hmma(float c[4],
                                     uint32_t a0, uint32_t a1, uint32_t a2, uint32_t a3,
                                     uint32_t b0, uint32_t b1) {
    asm volatile(
        "mma.sync.aligned.m16n8k16.row.col.f32.bf16.bf16.f32 "
        "{%0,%1,%2,%3}, {%4,%5,%6,%7}, {%8,%9}, {%0,%1,%2,%3};"
        : "+f"(c[0]), "+f"(c[1]), "+f"(c[2]), "+f"(c[3])
        : "r"(a0), "r"(a1), "r"(a2), "r"(a3), "r"(b0), "r"(b1));
}
__device__ __forceinline__ float2 ldsf2(uint32_t addr) {
    float2 v;
    asm volatile("ld.shared.v2.f32 {%0, %1}, [%2];" : "=f"(v.x), "=f"(v.y) : "r"(addr));
    return v;
}
__device__ __forceinline__ uint32_t smem_u32(const void* p) {
    uint32_t a;
    asm("{ .reg .u64 t; cvta.to.shared.u64 t, %1; cvt.u32.u64 %0, t; }" : "=r"(a) : "l"(p));
    return a;
}
// cp.async one 8-row x 512B chunk (warp-collective: lane = 16B column chunk)
__device__ __forceinline__ void issue_chunk(uint32_t rawW, const float* abase,
                                            int k, int lane) {
    uint32_t dbase = rawW + (uint32_t)(k & (RS - 1)) * 4096;
    const char* src = (const char*)(abase + (long long)k * 8 * E_DIM) + lane * 16;
    #pragma unroll
    for (int row = 0; row < 8; ++row) {
        uint32_t d = dbase + row * 512 + ((((uint32_t)lane) ^ (2u * (row & 3))) << 4);
        asm volatile("cp.async.cg.shared.global [%0], [%1], 16;"
                     :: "r"(d), "l"(src + (long long)row * E_DIM * 4) : "memory");
    }
    asm volatile("cp.async.commit_group;" ::: "memory");
}

__global__ __launch_bounds__(TPB, 3)
void decoder_hmma(const float* __restrict__ mw,
                  const float* __restrict__ bw,
                  float* __restrict__ out)
{
    extern __shared__ __align__(16) char dsm[];
    const uint32_t smb = smem_u32(dsm);
    float (*part)[4][16][16] = (float (*)[4][16][16])(dsm + SM_PART);
    float (*est)[16][16]     = (float (*)[16][16])(dsm + SM_EST);
    float* carry             = (float*)(dsm + SM_CARRY);

    const int tid = threadIdx.x;
    const int ws = tid >> 5;
    const int lane = tid & 31;
    const int r = lane >> 2;            // fragment row 0..7
    const int c = lane & 3;

    const uint32_t rawW = smb + SM_RAW + (uint32_t)ws * (RS * 4096);
    const uint32_t rot  = 2u * (uint32_t)(r & 3);
    const uint32_t q0   = (uint32_t)(c >> 1);
    const uint32_t rowoff = (uint32_t)r * 512 + (uint32_t)(c & 1) * 8;

    const int bc  = blockIdx.x / CTAS_PER_BC;
    const int cta = blockIdx.x - bc * CTAS_PER_BC;
    const int gi0   = (cta == 0) ? 0 : (37 * cta + 1);   // first group owned
    const int G_CTA = (cta == 0) ? 38 : 37;              // groups owned
    float* const obc = out + (long long)bc * OUT_PER_BC;
    const float* const abase =
        mw + ((long long)bc * FRAMES + (long long)gi0 * 16) * E_DIM + ws * 128;

    // start pipeline immediately: 4 chunks (2 full groups) in flight
    issue_chunk(rawW, abase, 0, lane);
    issue_chunk(rawW, abase, 1, lane);
    issue_chunk(rawW, abase, 2, lane);
    issue_chunk(rawW, abase, 3, lane);

    // ---- weight fragments in-kernel: bh -> registers, bl -> per-CTA scratch
    uint32_t bh[8][2][2];
    uint4* const myBloW = gBloS + (size_t)blockIdx.x * 1024 + ws * 32 + lane;
    {
        const int n0 = lane >> 2;
        const int kbase = ws * 128 + c * 2;
        #pragma unroll
        for (int ks = 0; ks < 8; ++ks) {
            uint32_t blq[4];
            #pragma unroll
            for (int nh = 0; nh < 2; ++nh)
                #pragma unroll
                for (int b = 0; b < 2; ++b) {
                    const float2 xv = __ldg((const float2*)
                        (bw + (n0 + nh * 8) * E_DIM + kbase + ks * 16 + b * 8));
                    uint32_t h = bf16hi2(xv.x, xv.y);
                    bh[ks][nh][b] = h;
                    blq[nh * 2 + b] = bf16lo2(xv.x, xv.y, h);
                }
            myBloW[ks * 128] = make_uint4(blq[0], blq[1], blq[2], blq[3]);
        }
    }
    const uint4* const blp = myBloW;   // read back (same thread, program order)

    // ---- carry-in: trailing half of frame (gi0*16 - 1), fp32 scalar dots.
    // Makes EVERY output element a plain exactly-once store (replay-safe).
    if (gi0 > 0) {
        int w = 8 + ws * 2 + (lane >> 4);            // each warp covers 2 w's
        int seg = (lane & 15) * 32;
        const float4* xr = (const float4*)(mw +
            ((long long)bc * FRAMES + (long long)gi0 * 16 - 1) * E_DIM + seg);
        const float4* wr = (const float4*)(bw + w * E_DIM + seg);
        float s = 0.f;
        #pragma unroll
        for (int i = 0; i < 8; ++i) {
            float4 a = __ldg(xr + i);
            float4 b = __ldg(wr + i);
            s += a.x * b.x + a.y * b.y + a.z * b.z + a.w * b.w;
        }
        #pragma unroll
        for (int off = 8; off; off >>= 1)
            s += __shfl_down_sync(0xffffffffu, s, off, 16);
        if ((lane & 15) == 0) carry[ws * 2 + (lane >> 4)] = s;
    } else if (tid < 8) {
        carry[tid] = 0.f;
    }
    __syncthreads();

    for (int g = 0; g < G_CTA; ++g) {
        if (g < G_CTA - 1) asm volatile("cp.async.wait_group 2;" ::: "memory");
        else               asm volatile("cp.async.wait_group 0;" ::: "memory");
        __syncwarp();   // publish async smem writes across lanes

        const uint32_t sA = rawW + (uint32_t)((2 * g) & (RS - 1)) * 4096 + rowoff;
        const uint32_t sB = rawW + (uint32_t)((2 * g + 1) & (RS - 1)) * 4096 + rowoff;

        float acc[2][4] = {{0.f, 0.f, 0.f, 0.f}, {0.f, 0.f, 0.f, 0.f}};
        #pragma unroll
        for (int ks = 0; ks < 8; ++ks) {
            uint32_t o0 = (((4u * ks + q0) ^ rot) << 4);
            uint32_t o2 = (((4u * ks + q0 + 2u) ^ rot) << 4);
            float2 x0 = ldsf2(sA + o0);   // rows r,    cols k0..k1
            float2 x1 = ldsf2(sB + o0);   // rows r+8,  cols k0..k1
            float2 x2 = ldsf2(sA + o2);   // rows r,    cols k8..k9
            float2 x3 = ldsf2(sB + o2);   // rows r+8,  cols k8..k9
            uint32_t ah0 = bf16hi2(x0.x, x0.y), al0 = bf16lo2(x0.x, x0.y, ah0);
            uint32_t ah1 = bf16hi2(x1.x, x1.y), al1 = bf16lo2(x1.x, x1.y, ah1);
            uint32_t ah2 = bf16hi2(x2.x, x2.y), al2 = bf16lo2(x2.x, x2.y, ah2);
            uint32_t ah3 = bf16hi2(x3.x, x3.y), al3 = bf16lo2(x3.x, x3.y, ah3);
            uint4 blv = blp[ks * 128];    // plain LDG, L1-hot, same-thread data
            hmma(acc[0], ah0, ah1, ah2, ah3, bh[ks][0][0], bh[ks][0][1]);
            hmma(acc[0], ah0, ah1, ah2, ah3, blv.x, blv.y);
            hmma(acc[0], al0, al1, al2, al3, bh[ks][0][0], bh[ks][0][1]);
            hmma(acc[1], ah0, ah1, ah2, ah3, bh[ks][1][0], bh[ks][1][1]);
            hmma(acc[1], ah0, ah1, ah2, ah3, blv.z, blv.w);
            hmma(acc[1], al0, al1, al2, al3, bh[ks][1][0], bh[ks][1][1]);
        }
        __syncwarp();   // all lanes done reading slots before refill overwrites
        if (g < G_CTA - 2) {   // refill BOTH chunks of group g+2 into freed slots
            issue_chunk(rawW, abase, 2 * g + 4, lane);
            issue_chunk(rawW, abase, 2 * g + 5, lane);
        }

        // ---- cross-warp K reduction (double-buffered, 2 barriers per group)
        float (*pb)[16][16] = part[g & 1];
        #pragma unroll
        for (int nh = 0; nh < 2; ++nh) {
            *(float2*)&pb[ws][r][c * 2 + nh * 8]     = make_float2(acc[nh][0], acc[nh][1]);
            *(float2*)&pb[ws][r + 8][c * 2 + nh * 8] = make_float2(acc[nh][2], acc[nh][3]);
        }
        __syncthreads();

        float (*eb)[16] = est[g & 1];
        #pragma unroll
        for (int h = 0; h < 2; ++h) {
            int e = tid + h * 128;
            int rr = e >> 4, cc = e & 15;
            eb[rr][cc] = pb[0][rr][cc] + pb[1][rr][cc]
                       + pb[2][rr][cc] + pb[3][rr][cc];
        }
        __syncthreads();

        // ---- overlap-add epilogue: ALL plain stores (carry chain, no atomics)
        const long long f0 = (long long)(gi0 + g) * 16;
        float* ob = obc + f0 * 8;
        if (tid < 120) {
            int k = tid >> 3, j = tid & 7;
            ob[(k + 1) * 8 + j] = eb[k][8 + j] + eb[k + 1][j];
        }
        if (tid < 8) {
            ob[tid] = carry[tid] + eb[0][tid];   // leading subframe (carry-in or chain)
            carry[tid] = eb[15][8 + tid];        // same-thread carry
        }
    }

    // bc-last CTA writes the final tail subframe (s = 16000)
    if (cta == CTAS_PER_BC - 1 && tid < 8)
        obc[(long long)FRAMES * 8 + tid] = carry[tid];
}

extern "C" void kernel_launch(void* const* d_in, const int* in_sizes, int n_in,
                              void* d_out, int out_size) {
    const float* mw = (const float*)d_in[0];   // [8,2,16000,512] f32
    const float* bw = (const float*)d_in[1];   // [16,512] f32
    float* out = (float*)d_out;                // [8,2,128008] f32

    cudaFuncSetAttribute(decoder_hmma, cudaFuncAttributeMaxDynamicSharedMemorySize, SM_TOTAL);
    decoder_hmma<<<NCTA, TPB, SM_TOTAL>>>(mw, bw, out);
}

// round 15
// speedup vs baseline: 1.0085x; 1.0085x over previous
#include <cuda_runtime.h>
#include <cstdint>

#define E_DIM 512
#define W_DIM 16
#define FRAMES 16000
#define NBC 16
#define OUT_PER_BC 128008
#define GROUPS_PER_BC 1000
#define CTAS_PER_BC 25
#define G_PER_CTA 40                              // 25 * 40 = 1000, perfectly uniform
#define NCTA (NBC * CTAS_PER_BC)                  // 400 <= 444 -> single wave
#define TPB 128
#define RS 4                                      // ring slots per warp (4 KB each)

// dynamic smem layout
#define SM_RAW   0                                // 4 warps * RS * 4096 = 65536
#define SM_PART  65536                            // [2][4][16][16] f32 = 8192
#define SM_EST   73728                            // [2][16][16] f32 = 2048
#define SM_CARRY 75776                            // 8 f32
#define SM_TOTAL 75808                            // <= 76800 -> 3 CTAs/SM

// bh: [term][ws][lane], term = ks*4+nh*2+b (registers)
// bl: [ks][ws][lane][nh*2+b] (L1-resident uint4 loads)
__device__ __align__(16) uint32_t gBhi[4096];
__device__ __align__(16) uint32_t gBlo[4096];

__device__ __forceinline__ uint32_t bf16hi2(float x0, float x1) {
    uint32_t h;
    asm("cvt.rn.bf16x2.f32 %0, %1, %2;" : "=r"(h) : "f"(x1), "f"(x0));
    return h;
}
__device__ __forceinline__ uint32_t bf16lo2(float x0, float x1, uint32_t h) {
    float h0 = __uint_as_float(h << 16);
    float h1 = __uint_as_float(h & 0xFFFF0000u);
    uint32_t l;
    asm("cvt.rn.bf16x2.f32 %0, %1, %2;" : "=r"(l) : "f"(x1 - h1), "f"(x0 - h0));
    return l;
}
__device__ __forceinline__ void hmma(float c[4],
                                     uint32_t a0, uint32_t a1, uint32_t a2, uint32_t a3,
                                     uint32_t b0, uint32_t b1) {
    asm volatile(
        "mma.sync.aligned.m16n8k16.row.col.f32.bf16.bf16.f32 "
        "{%0,%1,%2,%3}, {%4,%5,%6,%7}, {%8,%9}, {%0,%1,%2,%3};"
        : "+f"(c[0]), "+f"(c[1]), "+f"(c[2]), "+f"(c[3])
        : "r"(a0), "r"(a1), "r"(a2), "r"(a3), "r"(b0), "r"(b1));
}
__device__ __forceinline__ float2 ldsf2(uint32_t addr) {
    float2 v;
    asm volatile("ld.shared.v2.f32 {%0, %1}, [%2];" : "=f"(v.x), "=f"(v.y) : "r"(addr));
    return v;
}
__device__ __forceinline__ uint32_t smem_u32(const void* p) {
    uint32_t a;
    asm("{ .reg .u64 t; cvta.to.shared.u64 t, %1; cvt.u32.u64 %0, t; }" : "=r"(a) : "l"(p));
    return a;
}
// cp.async one 8-row x 512B chunk (warp-collective: lane = 16B column chunk)
__device__ __forceinline__ void issue_chunk(uint32_t rawW, const float* abase,
                                            int k, int lane) {
    uint32_t dbase = rawW + (uint32_t)(k & (RS - 1)) * 4096;
    const char* src = (const char*)(abase + (long long)k * 8 * E_DIM) + lane * 16;
    #pragma unroll
    for (int row = 0; row < 8; ++row) {
        uint32_t d = dbase + row * 512 + ((((uint32_t)lane) ^ (2u * (row & 3))) << 4);
        asm volatile("cp.async.cg.shared.global [%0], [%1], 16;"
                     :: "r"(d), "l"(src + (long long)row * E_DIM * 4) : "memory");
    }
    asm volatile("cp.async.commit_group;" ::: "memory");
}

// Fused prep: pack weight fragments + zero the per-bc edge locations
// (26 per bc: leading edges of the 25 CTAs + the bc tail). Every launch.
__global__ void prep_kernel(const float* __restrict__ bw, float* __restrict__ out) {
    int idx = blockIdx.x * blockDim.x + threadIdx.x;
    if (idx < 4096) {
        int lane = idx & 31;
        int rest = idx >> 5;
        int ws = rest & 3;
        int term = rest >> 2;
        int b = term & 1;
        int nh = (term >> 1) & 1;
        int ks = term >> 2;
        int n = (lane >> 2) + nh * 8;
        int k = ws * 128 + ks * 16 + (lane & 3) * 2 + b * 8;
        float x0 = bw[n * E_DIM + k];
        float x1 = bw[n * E_DIM + k + 1];
        uint32_t hi = bf16hi2(x0, x1);
        gBhi[idx] = hi;
        gBlo[(((ks * 4 + ws) * 32 + lane) << 2) + (nh * 2 + b)] = bf16lo2(x0, x1, hi);
        return;
    }
    int i = idx - 4096;
    if (i < NBC * 26 * 8) {
        int j = i & 7;
        int l = (i >> 3) % 26;
        int bc = i / (26 * 8);
        long long off = (l < 25) ? (long long)l * (G_PER_CTA * 128)   // CTA l leading edge
                                 : 128000;                            // bc tail (subframe 1000)
        out[(long long)bc * OUT_PER_BC + off + j] = 0.f;
    }
}

__global__ __launch_bounds__(TPB, 3)
void decoder_hmma(const float* __restrict__ mw, float* __restrict__ out)
{
    extern __shared__ __align__(16) char dsm[];
    const uint32_t smb = smem_u32(dsm);
    float (*part)[4][16][16] = (float (*)[4][16][16])(dsm + SM_PART);
    float (*est)[16][16]     = (float (*)[16][16])(dsm + SM_EST);
    float* carry             = (float*)(dsm + SM_CARRY);

    const int tid = threadIdx.x;
    const int ws = tid >> 5;
    const int lane = tid & 31;
    const int r = lane >> 2;            // fragment row 0..7
    const int c = lane & 3;

    const uint32_t rawW = smb + SM_RAW + (uint32_t)ws * (RS * 4096);
    const uint32_t rot  = 2u * (uint32_t)(r & 3);
    const uint32_t q0   = (uint32_t)(c >> 1);
    const uint32_t rowoff = (uint32_t)r * 512 + (uint32_t)(c & 1) * 8;

    // bh fragments resident in registers (32 regs)
    uint32_t bh[8][2][2];
    #pragma unroll
    for (int ks = 0; ks < 8; ++ks)
        #pragma unroll
        for (int nh = 0; nh < 2; ++nh)
            #pragma unroll
            for (int b = 0; b < 2; ++b)
                bh[ks][nh][b] = gBhi[((ks * 4 + nh * 2 + b) * 4 + ws) * 32 + lane];
    const uint4* const blp = (const uint4*)gBlo + ws * 32 + lane;

    const int bc  = blockIdx.x / CTAS_PER_BC;
    const int cta = blockIdx.x - bc * CTAS_PER_BC;
    const int gi0 = cta * G_PER_CTA;                 // uniform partition: 40 groups each
    float* const obc = out + (long long)bc * OUT_PER_BC;
    const float* const abase =
        mw + ((long long)bc * FRAMES + (long long)gi0 * 16) * E_DIM + ws * 128;

    // prologue: 4 chunks (2 full groups) in flight
    issue_chunk(rawW, abase, 0, lane);
    issue_chunk(rawW, abase, 1, lane);
    issue_chunk(rawW, abase, 2, lane);
    issue_chunk(rawW, abase, 3, lane);

    for (int g = 0; g < G_PER_CTA; ++g) {
        if (g < G_PER_CTA - 1) asm volatile("cp.async.wait_group 2;" ::: "memory");
        else                   asm volatile("cp.async.wait_group 0;" ::: "memory");
        __syncwarp();   // publish async smem writes across lanes

        const uint32_t sA = rawW + (uint32_t)((2 * g) & (RS - 1)) * 4096 + rowoff;
        const uint32_t sB = rawW + (uint32_t)((2 * g + 1) & (RS - 1)) * 4096 + rowoff;

        float acc[2][4] = {{0.f, 0.f, 0.f, 0.f}, {0.f, 0.f, 0.f, 0.f}};
        #pragma unroll
        for (int ks = 0; ks < 8; ++ks) {
            uint32_t o0 = (((4u * ks + q0) ^ rot) << 4);
            uint32_t o2 = (((4u * ks + q0 + 2u) ^ rot) << 4);
            float2 x0 = ldsf2(sA + o0);   // rows r,    cols k0..k1
            float2 x1 = ldsf2(sB + o0);   // rows r+8,  cols k0..k1
            float2 x2 = ldsf2(sA + o2);   // rows r,    cols k8..k9
            float2 x3 = ldsf2(sB + o2);   // rows r+8,  cols k8..k9
            uint32_t ah0 = bf16hi2(x0.x, x0.y), al0 = bf16lo2(x0.x, x0.y, ah0);
            uint32_t ah1 = bf16hi2(x1.x, x1.y), al1 = bf16lo2(x1.x, x1.y, ah1);
            uint32_t ah2 = bf16hi2(x2.x, x2.y), al2 = bf16lo2(x2.x, x2.y, ah2);
            uint32_t ah3 = bf16hi2(x3.x, x3.y), al3 = bf16lo2(x3.x, x3.y, ah3);
            uint4 blv = __ldg(blp + ks * 128);
            hmma(acc[0], ah0, ah1, ah2, ah3, bh[ks][0][0], bh[ks][0][1]);
            hmma(acc[0], ah0, ah1, ah2, ah3, blv.x, blv.y);
            hmma(acc[0], al0, al1, al2, al3, bh[ks][0][0], bh[ks][0][1]);
            hmma(acc[1], ah0, ah1, ah2, ah3, bh[ks][1][0], bh[ks][1][1]);
            hmma(acc[1], ah0, ah1, ah2, ah3, blv.z, blv.w);
            hmma(acc[1], al0, al1, al2, al3, bh[ks][1][0], bh[ks][1][1]);
        }
        __syncwarp();   // all lanes done reading slots before refill overwrites
        if (g < G_PER_CTA - 2) {   // refill BOTH chunks of group g+2 into freed slots
            issue_chunk(rawW, abase, 2 * g + 4, lane);
            issue_chunk(rawW, abase, 2 * g + 5, lane);
        }

        // ---- cross-warp K reduction (double-buffered, 2 barriers per group)
        float (*pb)[16][16] = part[g & 1];
        #pragma unroll
        for (int nh = 0; nh < 2; ++nh) {
            *(float2*)&pb[ws][r][c * 2 + nh * 8]     = make_float2(acc[nh][0], acc[nh][1]);
            *(float2*)&pb[ws][r + 8][c * 2 + nh * 8] = make_float2(acc[nh][2], acc[nh][3]);
        }
        __syncthreads();

        float (*eb)[16] = est[g & 1];
        #pragma unroll
        for (int h = 0; h < 2; ++h) {
            int e = tid + h * 128;
            int rr = e >> 4, cc = e & 15;
            eb[rr][cc] = pb[0][rr][cc] + pb[1][rr][cc]
                       + pb[2][rr][cc] + pb[3][rr][cc];
        }
        __syncthreads();

        // ---- overlap-add with carry chain (atomics ONLY at CTA edges)
        const long long f0 = (long long)(gi0 + g) * 16;
        float* ob = obc + f0 * 8;
        if (tid < 120) {
            int k = tid >> 3, j = tid & 7;
            ob[(k + 1) * 8 + j] = eb[k][8 + j] + eb[k + 1][j];
        }
        if (tid < 8) {
            if (g == 0) atomicAdd(ob + tid, eb[0][tid]);    // CTA leading edge (prep-zeroed)
            else        ob[tid] = carry[tid] + eb[0][tid];  // interior: plain store
            carry[tid] = eb[15][8 + tid];                   // same-thread carry
        }
    }

    // CTA trailing edge (prep-zeroed; neighbor CTA's leading atomic lands here too)
    if (tid < 8)
        atomicAdd(obc + (long long)(gi0 + G_PER_CTA) * 128 + tid, carry[tid]);
}

extern "C" void kernel_launch(void* const* d_in, const int* in_sizes, int n_in,
                              void* d_out, int out_size) {
    const float* mw = (const float*)d_in[0];   // [8,2,16000,512] f32
    const float* bw = (const float*)d_in[1];   // [16,512] f32
    float* out = (float*)d_out;                // [8,2,128008] f32

    cudaFuncSetAttribute(decoder_hmma, cudaFuncAttributeMaxDynamicSharedMemorySize, SM_TOTAL);

    int prep_threads = 4096 + NBC * 26 * 8;    // 7424
    prep_kernel<<<(prep_threads + 127) / 128, 128>>>(bw, out);
    decoder_hmma<<<NCTA, TPB, SM_TOTAL>>>(mw, out);
}

// round 16
// speedup vs baseline: 1.0446x; 1.0358x over previous
#include <cuda_runtime.h>
#include <cstdint>

#define E_DIM 512
#define W_DIM 16
#define FRAMES 16000
#define NBC 16
#define OUT_PER_BC 128008
#define GROUPS_PER_BC 1000
#define CTAS_PER_BC 37
#define NCTA (NBC * CTAS_PER_BC)                  // 592 = 148*4 -> exact single wave
#define TPB 128
#define RS 3                                      // ring slots per warp (4 KB each)

// dynamic smem layout (57 KB budget for 4 CTAs/SM)
#define SM_RAW   0                                // 4 warps * RS * 4096 = 49152
#define SM_PART  49152                            // [4][16][16] f32 = 4096
#define SM_EST   53248                            // [16][16] f32 = 1024
#define SM_CARRY 54272                            // 8 f32
#define SM_TOTAL 54304                            // *4 = 217216 <= 228KB -> 4 CTAs/SM

// bh: [term][ws][lane], term = ks*4+nh*2+b (registers)
// bl: [ks][ws][lane][nh*2+b] (L1-resident uint4 loads)
__device__ __align__(16) uint32_t gBhi[4096];
__device__ __align__(16) uint32_t gBlo[4096];

__device__ __forceinline__ uint32_t bf16hi2(float x0, float x1) {
    uint32_t h;
    asm("cvt.rn.bf16x2.f32 %0, %1, %2;" : "=r"(h) : "f"(x1), "f"(x0));
    return h;
}
__device__ __forceinline__ uint32_t bf16lo2(float x0, float x1, uint32_t h) {
    float h0 = __uint_as_float(h << 16);
    float h1 = __uint_as_float(h & 0xFFFF0000u);
    uint32_t l;
    asm("cvt.rn.bf16x2.f32 %0, %1, %2;" : "=r"(l) : "f"(x1 - h1), "f"(x0 - h0));
    return l;
}
__device__ __forceinline__ void hmma(float c[4],
                                     uint32_t a0, uint32_t a1, uint32_t a2, uint32_t a3,
                                     uint32_t b0, uint32_t b1) {
    asm volatile(
        "mma.sync.aligned.m16n8k16.row.col.f32.bf16.bf16.f32 "
        "{%0,%1,%2,%3}, {%4,%5,%6,%7}, {%8,%9}, {%0,%1,%2,%3};"
        : "+f"(c[0]), "+f"(c[1]), "+f"(c[2]), "+f"(c[3])
        : "r"(a0), "r"(a1), "r"(a2), "r"(a3), "r"(b0), "r"(b1));
}
__device__ __forceinline__ float2 ldsf2(uint32_t addr) {
    float2 v;
    asm volatile("ld.shared.v2.f32 {%0, %1}, [%2];" : "=f"(v.x), "=f"(v.y) : "r"(addr));
    return v;
}
__device__ __forceinline__ uint32_t smem_u32(const void* p) {
    uint32_t a;
    asm("{ .reg .u64 t; cvta.to.shared.u64 t, %1; cvt.u32.u64 %0, t; }" : "=r"(a) : "l"(p));
    return a;
}
// cp.async one 8-row x 512B chunk (warp-collective: lane = 16B column chunk)
__device__ __forceinline__ void issue_chunk(uint32_t rawW, const float* abase,
                                            int k, int lane) {
    uint32_t dbase = rawW + (uint32_t)(k % RS) * 4096;
    const char* src = (const char*)(abase + (long long)k * 8 * E_DIM) + lane * 16;
    #pragma unroll
    for (int row = 0; row < 8; ++row) {
        uint32_t d = dbase + row * 512 + ((((uint32_t)lane) ^ (2u * (row & 3))) << 4);
        asm volatile("cp.async.cg.shared.global [%0], [%1], 16;"
                     :: "r"(d), "l"(src + (long long)row * E_DIM * 4) : "memory");
    }
    asm volatile("cp.async.commit_group;" ::: "memory");
}

// Fused prep: pack weight fragments + zero the per-bc edge locations
// (38 per bc: leading edges of the 37 CTAs + the bc tail). Every launch.
__global__ void prep_kernel(const float* __restrict__ bw, float* __restrict__ out) {
    int idx = blockIdx.x * blockDim.x + threadIdx.x;
    if (idx < 4096) {
        int lane = idx & 31;
        int rest = idx >> 5;
        int ws = rest & 3;
        int term = rest >> 2;
        int b = term & 1;
        int nh = (term >> 1) & 1;
        int ks = term >> 2;
        int n = (lane >> 2) + nh * 8;
        int k = ws * 128 + ks * 16 + (lane & 3) * 2 + b * 8;
        float x0 = bw[n * E_DIM + k];
        float x1 = bw[n * E_DIM + k + 1];
        uint32_t hi = bf16hi2(x0, x1);
        gBhi[idx] = hi;
        gBlo[(((ks * 4 + ws) * 32 + lane) << 2) + (nh * 2 + b)] = bf16lo2(x0, x1, hi);
        return;
    }
    int i = idx - 4096;
    if (i < NBC * 38 * 8) {
        int j = i & 7;
        int l = (i >> 3) % 38;
        int bc = i / (38 * 8);
        long long off;
        if (l == 0)       off = 0;                          // CTA 0 leading edge
        else if (l < 37)  off = (long long)(27 * l + 1) * 128;  // CTA l leading edge
        else              off = 128000;                     // bc tail (subframe 1000)
        out[(long long)bc * OUT_PER_BC + off + j] = 0.f;
    }
}

__global__ __launch_bounds__(TPB, 4)
void decoder_hmma(const float* __restrict__ mw, float* __restrict__ out)
{
    extern __shared__ __align__(16) char dsm[];
    const uint32_t smb = smem_u32(dsm);
    float (*part)[16][16] = (float (*)[16][16])(dsm + SM_PART);
    float (*est)[16]      = (float (*)[16])(dsm + SM_EST);
    float* carry          = (float*)(dsm + SM_CARRY);

    const int tid = threadIdx.x;
    const int ws = tid >> 5;
    const int lane = tid & 31;
    const int r = lane >> 2;            // fragment row 0..7
    const int c = lane & 3;

    const uint32_t rawW = smb + SM_RAW + (uint32_t)ws * (RS * 4096);
    const uint32_t rot  = 2u * (uint32_t)(r & 3);
    const uint32_t q0   = (uint32_t)(c >> 1);
    const uint32_t rowoff = (uint32_t)r * 512 + (uint32_t)(c & 1) * 8;

    // bh fragments resident in registers (32 regs)
    uint32_t bh[8][2][2];
    #pragma unroll
    for (int ks = 0; ks < 8; ++ks)
        #pragma unroll
        for (int nh = 0; nh < 2; ++nh)
            #pragma unroll
            for (int b = 0; b < 2; ++b)
                bh[ks][nh][b] = gBhi[((ks * 4 + nh * 2 + b) * 4 + ws) * 32 + lane];
    const uint4* const blp = (const uint4*)gBlo + ws * 32 + lane;

    const int bc  = blockIdx.x / CTAS_PER_BC;
    const int cta = blockIdx.x - bc * CTAS_PER_BC;
    const int gi0   = (cta == 0) ? 0 : (27 * cta + 1);   // first group owned
    const int G_CTA = (cta == 0) ? 28 : 27;              // groups owned (max 28)
    float* const obc = out + (long long)bc * OUT_PER_BC;
    const float* const abase =
        mw + ((long long)bc * FRAMES + (long long)gi0 * 16) * E_DIM + ws * 128;

    // prologue: 2 chunks in flight (RS=3 ring)
    issue_chunk(rawW, abase, 0, lane);
    issue_chunk(rawW, abase, 1, lane);

    for (int g = 0; g < G_CTA; ++g) {
        if (g < G_CTA - 1) {
            issue_chunk(rawW, abase, 2 * g + 2, lane);
            asm volatile("cp.async.wait_group 1;" ::: "memory");
        } else {
            asm volatile("cp.async.wait_group 0;" ::: "memory");
        }
        __syncwarp();   // publish async smem writes across lanes

        const uint32_t sA = rawW + (uint32_t)((2 * g) % RS) * 4096 + rowoff;
        const uint32_t sB = rawW + (uint32_t)((2 * g + 1) % RS) * 4096 + rowoff;

        float acc[2][4] = {{0.f, 0.f, 0.f, 0.f}, {0.f, 0.f, 0.f, 0.f}};
        #pragma unroll
        for (int ks = 0; ks < 8; ++ks) {
            uint32_t o0 = (((4u * ks + q0) ^ rot) << 4);
            uint32_t o2 = (((4u * ks + q0 + 2u) ^ rot) << 4);
            float2 x0 = ldsf2(sA + o0);   // rows r,    cols k0..k1
            float2 x1 = ldsf2(sB + o0);   // rows r+8,  cols k0..k1
            float2 x2 = ldsf2(sA + o2);   // rows r,    cols k8..k9
            float2 x3 = ldsf2(sB + o2);   // rows r+8,  cols k8..k9
            uint32_t ah0 = bf16hi2(x0.x, x0.y), al0 = bf16lo2(x0.x, x0.y, ah0);
            uint32_t ah1 = bf16hi2(x1.x, x1.y), al1 = bf16lo2(x1.x, x1.y, ah1);
            uint32_t ah2 = bf16hi2(x2.x, x2.y), al2 = bf16lo2(x2.x, x2.y, ah2);
            uint32_t ah3 = bf16hi2(x3.x, x3.y), al3 = bf16lo2(x3.x, x3.y, ah3);
            uint4 blv = __ldg(blp + ks * 128);
            hmma(acc[0], ah0, ah1, ah2, ah3, bh[ks][0][0], bh[ks][0][1]);
            hmma(acc[0], ah0, ah1, ah2, ah3, blv.x, blv.y);
            hmma(acc[0], al0, al1, al2, al3, bh[ks][0][0], bh[ks][0][1]);
            hmma(acc[1], ah0, ah1, ah2, ah3, bh[ks][1][0], bh[ks][1][1]);
            hmma(acc[1], ah0, ah1, ah2, ah3, blv.z, blv.w);
            hmma(acc[1], al0, al1, al2, al3, bh[ks][1][0], bh[ks][1][1]);
        }
        __syncwarp();   // all lanes done reading slots before refill overwrites
        if (g < G_CTA - 1) issue_chunk(rawW, abase, 2 * g + 3, lane);

        // ---- cross-warp K reduction (single-buffered, 2 barriers: safe because
        // est/part writes of group g+1 happen only after g+1's first barrier,
        // which every thread reaches only after finishing g's epilogue reads)
        #pragma unroll
        for (int nh = 0; nh < 2; ++nh) {
            *(float2*)&part[ws][r][c * 2 + nh * 8]     = make_float2(acc[nh][0], acc[nh][1]);
            *(float2*)&part[ws][r + 8][c * 2 + nh * 8] = make_float2(acc[nh][2], acc[nh][3]);
        }
        __syncthreads();

        #pragma unroll
        for (int h = 0; h < 2; ++h) {
            int e = tid + h * 128;
            int rr = e >> 4, cc = e & 15;
            est[rr][cc] = part[0][rr][cc] + part[1][rr][cc]
                        + part[2][rr][cc] + part[3][rr][cc];
        }
        __syncthreads();

        // ---- overlap-add with carry chain (atomics ONLY at CTA edges)
        const long long f0 = (long long)(gi0 + g) * 16;
        float* ob = obc + f0 * 8;
        if (tid < 120) {
            int k = tid >> 3, j = tid & 7;
            ob[(k + 1) * 8 + j] = est[k][8 + j] + est[k + 1][j];
        }
        if (tid < 8) {
            if (g == 0) atomicAdd(ob + tid, est[0][tid]);   // CTA leading edge (prep-zeroed)
            else        ob[tid] = carry[tid] + est[0][tid]; // interior: plain store
            carry[tid] = est[15][8 + tid];                  // same-thread carry
        }
    }

    // CTA trailing edge (prep-zeroed; neighbor CTA's leading atomic lands here too)
    if (tid < 8)
        atomicAdd(obc + (long long)(gi0 + G_CTA) * 128 + tid, carry[tid]);
}

extern "C" void kernel_launch(void* const* d_in, const int* in_sizes, int n_in,
                              void* d_out, int out_size) {
    const float* mw = (const float*)d_in[0];   // [8,2,16000,512] f32
    const float* bw = (const float*)d_in[1];   // [16,512] f32
    float* out = (float*)d_out;                // [8,2,128008] f32

    cudaFuncSetAttribute(decoder_hmma, cudaFuncAttributeMaxDynamicSharedMemorySize, SM_TOTAL);

    int prep_threads = 4096 + NBC * 38 * 8;    // 8960
    prep_kernel<<<(prep_threads + 127) / 128, 128>>>(bw, out);
    decoder_hmma<<<NCTA, TPB, SM_TOTAL>>>(mw, out);
}